// round 3
// baseline (speedup 1.0000x reference)
#include <cuda_runtime.h>
#include <cuda_bf16.h>
#include <math.h>

// skipgram loss: one warp per TWO batch elements (ILP-2), interleaved gathers.
// R3: lengthen the per-warp row-gather burst (24 row loads behind one index
// stall instead of 12) to raise DRAM duty cycle from 76%.
// Inputs: u_weight[V*D] f32, v_weight[V*D] f32, u_pos[B] i32, v_pos[B] i32,
// v_neg[B*N] i32, batch_size. D=128, N=10. B from in_sizes[2].

#define D 128
#define NNEG 10
#define WARPS_PER_BLOCK 8
#define BLOCK_THREADS (WARPS_PER_BLOCK * 32)

__device__ __forceinline__ float log_sigmoid_f(float x) {
    return fminf(x, 0.0f) - log1pf(expf(-fabsf(x)));
}

__device__ __forceinline__ float dot4(const float4 a, const float4 b) {
    return a.x * b.x + a.y * b.y + a.z * b.z + a.w * b.w;
}

__global__ __launch_bounds__(BLOCK_THREADS)
void skipgram_kernel(const float* __restrict__ u_w,
                     const float* __restrict__ v_w,
                     const int* __restrict__ u_pos,
                     const int* __restrict__ v_pos,
                     const int* __restrict__ v_neg,
                     float* __restrict__ out,
                     int B, float neg_inv_B) {
    const int gwarp = (blockIdx.x * BLOCK_THREADS + threadIdx.x) >> 5;
    const int lane  = threadIdx.x & 31;
    const int wid   = threadIdx.x >> 5;

    const int e0 = gwarp * 2;
    const int e1 = e0 + 1;

    float val = 0.0f;
    if (e0 < B) {
        const bool has1 = (e1 < B);
        const int e1c = has1 ? e1 : e0;  // clamp; discard later

        // ---- Phase 1: ALL index loads for both elements (one stall) ----
        const size_t ui0 = (size_t)__ldcs(u_pos + e0);
        const size_t ui1 = (size_t)__ldcs(u_pos + e1c);
        const size_t vi0 = (size_t)__ldcs(v_pos + e0);
        const size_t vi1 = (size_t)__ldcs(v_pos + e1c);
        int nidx0[NNEG], nidx1[NNEG];
        const int* nb0 = v_neg + (size_t)e0 * NNEG;
        const int* nb1 = v_neg + (size_t)e1c * NNEG;
        #pragma unroll
        for (int n = 0; n < NNEG; n++) { nidx0[n] = __ldcs(nb0 + n); nidx1[n] = __ldcs(nb1 + n); }

        // ---- Phase 2: interleaved row gathers (24 LDG.128 burst) ----
        const float4 u40 = reinterpret_cast<const float4*>(u_w + ui0 * D)[lane];
        const float4 u41 = reinterpret_cast<const float4*>(u_w + ui1 * D)[lane];
        const float4 v40 = reinterpret_cast<const float4*>(v_w + vi0 * D)[lane];
        const float4 v41 = reinterpret_cast<const float4*>(v_w + vi1 * D)[lane];

        float pdot0 = dot4(u40, v40);
        float pdot1 = dot4(u41, v41);

        float nacc0 = 0.0f, nacc1 = 0.0f;
        #pragma unroll
        for (int n = 0; n < NNEG; n++) {
            const float4 w0 = reinterpret_cast<const float4*>(v_w + (size_t)nidx0[n] * D)[lane];
            const float4 w1 = reinterpret_cast<const float4*>(v_w + (size_t)nidx1[n] * D)[lane];
            nacc0 += dot4(u40, w0);
            nacc1 += dot4(u41, w1);
        }

        // ---- Reduce: one butterfly pass over all four accumulators ----
        #pragma unroll
        for (int off = 16; off > 0; off >>= 1) {
            pdot0 += __shfl_xor_sync(0xffffffffu, pdot0, off);
            nacc0 += __shfl_xor_sync(0xffffffffu, nacc0, off);
            pdot1 += __shfl_xor_sync(0xffffffffu, pdot1, off);
            nacc1 += __shfl_xor_sync(0xffffffffu, nacc1, off);
        }

        float l0 = log_sigmoid_f(pdot0 * (1.0f / (float)D)) +
                   log_sigmoid_f(-nacc0 * (1.0f / (float)NNEG));
        float l1 = log_sigmoid_f(pdot1 * (1.0f / (float)D)) +
                   log_sigmoid_f(-nacc1 * (1.0f / (float)NNEG));
        if (!has1) l1 = 0.0f;
        val = (l0 + l1) * neg_inv_B;
    }

    __shared__ float sm[WARPS_PER_BLOCK];
    if (lane == 0) sm[wid] = val;
    __syncthreads();
    if (threadIdx.x < WARPS_PER_BLOCK) {
        float v = sm[threadIdx.x];
        #pragma unroll
        for (int off = WARPS_PER_BLOCK / 2; off > 0; off >>= 1)
            v += __shfl_xor_sync(0xffu, v, off);
        if (threadIdx.x == 0) atomicAdd(out, v);
    }
}

extern "C" void kernel_launch(void* const* d_in, const int* in_sizes, int n_in,
                              void* d_out, int out_size) {
    const float* u_w  = (const float*)d_in[0];
    const float* v_w  = (const float*)d_in[1];
    const int* u_pos  = (const int*)d_in[2];
    const int* v_pos  = (const int*)d_in[3];
    const int* v_neg  = (const int*)d_in[4];
    float* out        = (float*)d_out;

    const int B = in_sizes[2];

    cudaMemsetAsync(out, 0, sizeof(float), 0);

    const int pairs = (B + 1) / 2;                       // warps needed
    const int blocks = (pairs + WARPS_PER_BLOCK - 1) / WARPS_PER_BLOCK;
    skipgram_kernel<<<blocks, BLOCK_THREADS>>>(u_w, v_w, u_pos, v_pos, v_neg,
                                               out, B, -1.0f / (float)B);
}

// round 4
// speedup vs baseline: 1.0668x; 1.0668x over previous
#include <cuda_runtime.h>
#include <cuda_bf16.h>
#include <math.h>

// skipgram loss. R4: one warp handles TWO batch elements SEQUENTIALLY
// (not interleaved -- R3 showed interleaving blows registers/occupancy).
// Both elements' indices are loaded up front so element 1's 12-row gather
// burst starts with no index-load stall. Indices loaded as int2 (8B-aligned).

#define D 128
#define NNEG 10
#define WARPS_PER_BLOCK 8
#define BLOCK_THREADS (WARPS_PER_BLOCK * 32)

__device__ __forceinline__ float log_sigmoid_f(float x) {
    return fminf(x, 0.0f) - log1pf(expf(-fabsf(x)));
}

__device__ __forceinline__ float dot4(const float4 a, const float4 b) {
    return a.x * b.x + a.y * b.y + a.z * b.z + a.w * b.w;
}

// Compute per-element loss term given resolved indices.
__device__ __forceinline__ float element_loss(const float* __restrict__ u_w,
                                              const float* __restrict__ v_w,
                                              int ui, int vi, const int* nidx,
                                              int lane) {
    const float4 u4 = reinterpret_cast<const float4*>(u_w + (size_t)ui * D)[lane];
    const float4 v4 = reinterpret_cast<const float4*>(v_w + (size_t)vi * D)[lane];
    float pdot = dot4(u4, v4);
    float nacc = 0.0f;
    #pragma unroll
    for (int n = 0; n < NNEG; n++) {
        const float4 w4 = reinterpret_cast<const float4*>(v_w + (size_t)nidx[n] * D)[lane];
        nacc += dot4(u4, w4);
    }
    #pragma unroll
    for (int off = 16; off > 0; off >>= 1) {
        pdot += __shfl_xor_sync(0xffffffffu, pdot, off);
        nacc += __shfl_xor_sync(0xffffffffu, nacc, off);
    }
    return log_sigmoid_f(pdot * (1.0f / (float)D)) +
           log_sigmoid_f(-nacc * (1.0f / (float)NNEG));
}

__global__ __launch_bounds__(BLOCK_THREADS)
void skipgram_kernel(const float* __restrict__ u_w,
                     const float* __restrict__ v_w,
                     const int* __restrict__ u_pos,
                     const int* __restrict__ v_pos,
                     const int* __restrict__ v_neg,
                     float* __restrict__ out,
                     int B, float neg_inv_B) {
    const int gwarp = (blockIdx.x * BLOCK_THREADS + threadIdx.x) >> 5;
    const int lane  = threadIdx.x & 31;
    const int wid   = threadIdx.x >> 5;

    const int e0 = gwarp * 2;
    const int e1 = e0 + 1;

    float val = 0.0f;
    if (e0 < B) {
        const bool has1 = (e1 < B);
        const int e1c = has1 ? e1 : e0;

        // ---- All index loads for BOTH elements, issued together ----
        const int ui0 = u_pos[e0];
        const int ui1 = u_pos[e1c];
        const int vi0 = v_pos[e0];
        const int vi1 = v_pos[e1c];

        // v_neg rows are 40B apart -> always 8B aligned: use int2 loads.
        int nidx0[NNEG], nidx1[NNEG];
        const int2* nb0 = reinterpret_cast<const int2*>(v_neg + (size_t)e0 * NNEG);
        const int2* nb1 = reinterpret_cast<const int2*>(v_neg + (size_t)e1c * NNEG);
        #pragma unroll
        for (int n = 0; n < NNEG / 2; n++) {
            const int2 a = nb0[n];
            const int2 b = nb1[n];
            nidx0[2 * n] = a.x; nidx0[2 * n + 1] = a.y;
            nidx1[2 * n] = b.x; nidx1[2 * n + 1] = b.y;
        }

        // ---- Element 0: 12-row gather burst + reduce ----
        float l = element_loss(u_w, v_w, ui0, vi0, nidx0, lane);
        // ---- Element 1: indices already resolved, burst starts immediately ----
        if (has1)
            l += element_loss(u_w, v_w, ui1, vi1, nidx1, lane);

        val = l * neg_inv_B;
    }

    __shared__ float sm[WARPS_PER_BLOCK];
    if (lane == 0) sm[wid] = val;
    __syncthreads();
    if (threadIdx.x < WARPS_PER_BLOCK) {
        float v = sm[threadIdx.x];
        #pragma unroll
        for (int off = WARPS_PER_BLOCK / 2; off > 0; off >>= 1)
            v += __shfl_xor_sync(0xffu, v, off);
        if (threadIdx.x == 0) atomicAdd(out, v);
    }
}

extern "C" void kernel_launch(void* const* d_in, const int* in_sizes, int n_in,
                              void* d_out, int out_size) {
    const float* u_w  = (const float*)d_in[0];
    const float* v_w  = (const float*)d_in[1];
    const int* u_pos  = (const int*)d_in[2];
    const int* v_pos  = (const int*)d_in[3];
    const int* v_neg  = (const int*)d_in[4];
    float* out        = (float*)d_out;

    const int B = in_sizes[2];

    cudaMemsetAsync(out, 0, sizeof(float), 0);

    const int pairs = (B + 1) / 2;
    const int blocks = (pairs + WARPS_PER_BLOCK - 1) / WARPS_PER_BLOCK;
    skipgram_kernel<<<blocks, BLOCK_THREADS>>>(u_w, v_w, u_pos, v_pos, v_neg,
                                               out, B, -1.0f / (float)B);
}

// round 5
// speedup vs baseline: 1.0708x; 1.0038x over previous
#include <cuda_runtime.h>
#include <cuda_bf16.h>
#include <math.h>

// skipgram loss: one warp per batch element (R1 structure -- fastest measured).
// Pure random-gather HBM kernel pinned at ~76% DRAM busy (6.05 TB/s), which
// R1-R4 established as the efficiency ceiling for random 512B row gathers.
// R5: consolidation -- int2 neg-index loads (rows are 40B apart, 8B aligned),
// minimal registers (32) for max occupancy (64 warps/SM).

#define D 128
#define NNEG 10
#define WARPS_PER_BLOCK 8
#define BLOCK_THREADS (WARPS_PER_BLOCK * 32)

__device__ __forceinline__ float log_sigmoid_f(float x) {
    return fminf(x, 0.0f) - log1pf(expf(-fabsf(x)));
}

__device__ __forceinline__ float dot4(const float4 a, const float4 b) {
    return a.x * b.x + a.y * b.y + a.z * b.z + a.w * b.w;
}

__global__ __launch_bounds__(BLOCK_THREADS)
void skipgram_kernel(const float* __restrict__ u_w,
                     const float* __restrict__ v_w,
                     const int* __restrict__ u_pos,
                     const int* __restrict__ v_pos,
                     const int* __restrict__ v_neg,
                     float* __restrict__ out,
                     int B, float neg_inv_B) {
    const int gwarp = (blockIdx.x * BLOCK_THREADS + threadIdx.x) >> 5;
    const int lane  = threadIdx.x & 31;
    const int wid   = threadIdx.x >> 5;

    float val = 0.0f;
    if (gwarp < B) {
        const size_t ui = (size_t)u_pos[gwarp];
        const size_t vi = (size_t)v_pos[gwarp];

        // Neg indices: 10 ints, base always 8B-aligned -> 5x LDG.64.
        int nidx[NNEG];
        const int2* nb = reinterpret_cast<const int2*>(v_neg + (size_t)gwarp * NNEG);
        #pragma unroll
        for (int n = 0; n < NNEG / 2; n++) {
            const int2 a = nb[n];
            nidx[2 * n] = a.x;
            nidx[2 * n + 1] = a.y;
        }

        // Row gathers: one warp fetches a full 512B row per LDG.128.
        const float4 u4 = reinterpret_cast<const float4*>(u_w + ui * D)[lane];
        const float4 v4 = reinterpret_cast<const float4*>(v_w + vi * D)[lane];

        float pdot = dot4(u4, v4);

        float nacc = 0.0f;
        #pragma unroll
        for (int n = 0; n < NNEG; n++) {
            const float4 w4 = reinterpret_cast<const float4*>(v_w + (size_t)nidx[n] * D)[lane];
            nacc += dot4(u4, w4);
        }

        // One butterfly pass reduces both accumulators.
        #pragma unroll
        for (int off = 16; off > 0; off >>= 1) {
            pdot += __shfl_xor_sync(0xffffffffu, pdot, off);
            nacc += __shfl_xor_sync(0xffffffffu, nacc, off);
        }

        const float score  = pdot * (1.0f / (float)D);   // mean over D
        const float nscore = nacc * (1.0f / (float)NNEG);// mean over N
        val = (log_sigmoid_f(score) + log_sigmoid_f(-nscore)) * neg_inv_B;
    }

    // Block reduction -> one atomicAdd per block.
    __shared__ float sm[WARPS_PER_BLOCK];
    if (lane == 0) sm[wid] = val;
    __syncthreads();
    if (threadIdx.x < WARPS_PER_BLOCK) {
        float v = sm[threadIdx.x];
        #pragma unroll
        for (int off = WARPS_PER_BLOCK / 2; off > 0; off >>= 1)
            v += __shfl_xor_sync(0xffu, v, off);
        if (threadIdx.x == 0) atomicAdd(out, v);
    }
}

extern "C" void kernel_launch(void* const* d_in, const int* in_sizes, int n_in,
                              void* d_out, int out_size) {
    const float* u_w  = (const float*)d_in[0];
    const float* v_w  = (const float*)d_in[1];
    const int* u_pos  = (const int*)d_in[2];
    const int* v_pos  = (const int*)d_in[3];
    const int* v_neg  = (const int*)d_in[4];
    float* out        = (float*)d_out;

    const int B = in_sizes[2];

    cudaMemsetAsync(out, 0, sizeof(float), 0);

    const int blocks = (B + WARPS_PER_BLOCK - 1) / WARPS_PER_BLOCK;
    skipgram_kernel<<<blocks, BLOCK_THREADS>>>(u_w, v_w, u_pos, v_pos, v_neg,
                                               out, B, -1.0f / (float)B);
}